// round 3
// baseline (speedup 1.0000x reference)
#include <cuda_runtime.h>
#include <cuda_bf16.h>

#define NN   4096
#define FF   256
#define KH   8
#define FPD  64
#define KFP  512   // K*FP

// ---------------- scratch (static device globals; no allocation) -------------
__device__ float g_xe[NN * KFP];            // 8 MB: xe[n][k*64+f]
__device__ float g_hl[KH * NN];             // hl[k][n]
__device__ float g_hr[KH * NN];             // hr[k][n]
__device__ unsigned char g_mask[NN * NN];   // 16 MB canonical uint8 mask
__device__ int g_mask_fmt;                  // 0=uint8, 1=int32, 2=float32

// ---------------- Kernel 0: probe mask dtype --------------------------------
// Harness widens jax bool to one of {uint8, int32, float32}. Mask content is
// random 0/1 so the first 4096 32-bit words separate the encodings exactly:
//   int32  : every word is 0 or 1
//   float32: every word is 0x00000000 or 0x3F800000
//   uint8  : words are packed 0/1 bytes (e.g. 0x00010100) -> neither
__global__ void detect_mask_fmt(const unsigned int* __restrict__ m) {
    int lane = threadIdx.x;
    bool not_i32 = false, not_f32 = false;
    for (int i = lane; i < 4096; i += 32) {
        unsigned int w = m[i];
        if (w > 1u) not_i32 = true;
        if (w != 0u && w != 0x3F800000u) not_f32 = true;
    }
    unsigned a = __ballot_sync(0xFFFFFFFFu, not_i32);
    unsigned b = __ballot_sync(0xFFFFFFFFu, not_f32);
    if (lane == 0) g_mask_fmt = (a == 0u) ? 1 : ((b == 0u) ? 2 : 0);
}

// ---------------- Kernel 0b: canonicalize mask to uint8 ---------------------
__global__ void __launch_bounds__(256) mask_canon(const void* __restrict__ m) {
    int i = blockIdx.x * blockDim.x + threadIdx.x;   // 0 .. NN*NN-1
    int fmt = g_mask_fmt;
    unsigned char v;
    if (fmt == 1)      v = (unsigned char)(((const int*)m)[i] != 0);
    else if (fmt == 2) v = (unsigned char)(((const float*)m)[i] != 0.0f);
    else               v = (unsigned char)(((const unsigned char*)m)[i] != 0);
    g_mask[i] = v;
}

// ---------------- Kernel A: xe = x @ W^T + b  (SGEMM 4096x512x256) ----------
// BM=128, BN=64, BK=16, 256 threads, per-thread 8x4
__global__ void __launch_bounds__(256) gemm_xe(const float* __restrict__ x,
                                               const float* __restrict__ W,
                                               const float* __restrict__ b) {
    __shared__ float a_s[16][128];
    __shared__ float b_s[16][64];
    const int tid = threadIdx.x;
    const int tx = tid & 15;   // 16 col groups of 4
    const int ty = tid >> 4;   // 16 row groups of 8
    const int row0 = blockIdx.x * 128;
    const int col0 = blockIdx.y * 64;

    float acc[8][4];
#pragma unroll
    for (int i = 0; i < 8; i++)
#pragma unroll
        for (int j = 0; j < 4; j++) acc[i][j] = 0.0f;

    for (int k0 = 0; k0 < FF; k0 += 16) {
#pragma unroll
        for (int u = 0; u < 2; u++) {
            int f4 = tid * 2 + u;          // 0..511
            int r  = f4 >> 2;              // 0..127
            int c4 = f4 & 3;               // 0..3
            float4 v = *(const float4*)&x[(size_t)(row0 + r) * FF + k0 + c4 * 4];
            a_s[c4 * 4 + 0][r] = v.x;
            a_s[c4 * 4 + 1][r] = v.y;
            a_s[c4 * 4 + 2][r] = v.z;
            a_s[c4 * 4 + 3][r] = v.w;
        }
        {
            int o  = tid >> 2;             // 0..63
            int c4 = tid & 3;              // 0..3
            float4 v = *(const float4*)&W[(size_t)(col0 + o) * FF + k0 + c4 * 4];
            b_s[c4 * 4 + 0][o] = v.x;
            b_s[c4 * 4 + 1][o] = v.y;
            b_s[c4 * 4 + 2][o] = v.z;
            b_s[c4 * 4 + 3][o] = v.w;
        }
        __syncthreads();
#pragma unroll
        for (int kk = 0; kk < 16; kk++) {
            float a_f[8], b_f[4];
#pragma unroll
            for (int i = 0; i < 8; i++) a_f[i] = a_s[kk][ty * 8 + i];
#pragma unroll
            for (int j = 0; j < 4; j++) b_f[j] = b_s[kk][tx * 4 + j];
#pragma unroll
            for (int i = 0; i < 8; i++)
#pragma unroll
                for (int j = 0; j < 4; j++) acc[i][j] += a_f[i] * b_f[j];
        }
        __syncthreads();
    }
    float4 bias = *(const float4*)&b[col0 + tx * 4];
#pragma unroll
    for (int i = 0; i < 8; i++) {
        float4 v;
        v.x = acc[i][0] + bias.x;
        v.y = acc[i][1] + bias.y;
        v.z = acc[i][2] + bias.z;
        v.w = acc[i][3] + bias.w;
        *(float4*)&g_xe[(size_t)(row0 + ty * 8 + i) * KFP + col0 + tx * 4] = v;
    }
}

// ---------------- Kernel B: hl[k][n], hr[k][n] ------------------------------
__global__ void __launch_bounds__(256) hlr_kernel(const float* __restrict__ al,
                                                  const float* __restrict__ ar) {
    int wid  = blockIdx.x * 8 + (threadIdx.x >> 5);  // 0..32767
    int lane = threadIdx.x & 31;
    int k = wid >> 12;      // wid / 4096
    int n = wid & 4095;
    float x0 = g_xe[(size_t)n * KFP + k * FPD + lane];
    float x1 = g_xe[(size_t)n * KFP + k * FPD + 32 + lane];
    float l = x0 * al[k * FPD + lane] + x1 * al[k * FPD + 32 + lane];
    float r = x0 * ar[k * FPD + lane] + x1 * ar[k * FPD + 32 + lane];
#pragma unroll
    for (int off = 16; off; off >>= 1) {
        l += __shfl_xor_sync(0xFFFFFFFFu, l, off);
        r += __shfl_xor_sync(0xFFFFFFFFu, r, off);
    }
    if (lane == 0) {
        g_hl[k * NN + n] = l;
        g_hr[k * NN + n] = r;
    }
}

// ---------------- Kernel C: masked additive attention + PV + ELU ------------
// grid (128, 8): block = 32 rows of one head. 8 warps x 4 rows each.
// No max subtraction needed: |scores| <= ~10 so exp is safe in fp32 and the
// exp(max) factor cancels exactly in softmax. Masked entries: p = 0 exactly.
__global__ void __launch_bounds__(256) gat_attn(float* __restrict__ out) {
    const int k    = blockIdx.y;
    const int n0   = blockIdx.x * 32;
    const int tid  = threadIdx.x;
    const int warp = tid >> 5;
    const int lane = tid & 31;
    const int nbase = n0 + warp * 4;

    __shared__ __align__(16) float s_xe[32 * 64];   // 8 KB m-chunk of xe (this head)
    __shared__ __align__(16) float s_p[8][128];     // per-warp p[j][r] packed float4
    __shared__ float s_hr[32];

    float hl[4];
#pragma unroll
    for (int r = 0; r < 4; r++) hl[r] = g_hl[k * NN + nbase + r];

    float acc[4][2];
    float rs[4];
#pragma unroll
    for (int r = 0; r < 4; r++) { acc[r][0] = 0.f; acc[r][1] = 0.f; rs[r] = 0.f; }

#pragma unroll 1
    for (int m0 = 0; m0 < NN; m0 += 32) {
        // cooperative load of xe chunk: 32 m-rows x 64 f
#pragma unroll
        for (int u = 0; u < 2; u++) {
            int idx = tid + u * 256;       // 0..511 float4 slots
            int mi  = idx >> 4;            // 0..31
            int f4  = idx & 15;            // 0..15
            float4 v = *(const float4*)&g_xe[(size_t)(m0 + mi) * KFP + k * FPD + f4 * 4];
            *(float4*)&s_xe[mi * 64 + f4 * 4] = v;
        }
        if (tid < 32) s_hr[tid] = g_hr[k * NN + m0 + tid];
        __syncthreads();

        // scores + exp for this warp's 4 rows, lane = m within chunk
        float hrj = s_hr[lane];
        float pv[4];
#pragma unroll
        for (int r = 0; r < 4; r++) {
            float s = hl[r] + hrj;
            s = fmaxf(s, 0.2f * s);                               // LeakyReLU(0.2)
            unsigned char mb = g_mask[(size_t)(nbase + r) * NN + m0 + lane];
            float p = mb ? __expf(s) : 0.0f;                      // masked -> exactly 0
            rs[r] += p;
            pv[r] = p;
        }
        *(float4*)&s_p[warp][lane * 4] = make_float4(pv[0], pv[1], pv[2], pv[3]);
        __syncwarp();

        // rank-32 update: acc[r][c] += p[r][j] * xe[j][2*lane+c]
#pragma unroll
        for (int j = 0; j < 32; j++) {
            float4 p4 = *(const float4*)&s_p[warp][j * 4];
            float2 v  = *(const float2*)&s_xe[j * 64 + lane * 2];
            acc[0][0] += p4.x * v.x; acc[0][1] += p4.x * v.y;
            acc[1][0] += p4.y * v.x; acc[1][1] += p4.y * v.y;
            acc[2][0] += p4.z * v.x; acc[2][1] += p4.z * v.y;
            acc[3][0] += p4.w * v.x; acc[3][1] += p4.w * v.y;
        }
        __syncthreads();
    }

    // normalize + double ELU + store
#pragma unroll
    for (int r = 0; r < 4; r++) {
        float s = rs[r];
#pragma unroll
        for (int off = 16; off; off >>= 1) s += __shfl_xor_sync(0xFFFFFFFFu, s, off);
        float inv = 1.0f / s;
#pragma unroll
        for (int c = 0; c < 2; c++) {
            float z = acc[r][c] * inv;
            z = z > 0.0f ? z : expm1f(z);   // elu
            z = z > 0.0f ? z : expm1f(z);   // elu again (non-final layer)
            out[(size_t)(nbase + r) * KFP + k * FPD + lane * 2 + c] = z;
        }
    }
}

// ---------------- optional: mask passthrough as float -----------------------
__global__ void mask_to_float(float* __restrict__ o, int n4) {
    int i = blockIdx.x * blockDim.x + threadIdx.x;
    if (i < n4) {
        uchar4 v = *(const uchar4*)(g_mask + (size_t)i * 4);
        float4 f;
        f.x = v.x ? 1.0f : 0.0f;
        f.y = v.y ? 1.0f : 0.0f;
        f.z = v.z ? 1.0f : 0.0f;
        f.w = v.w ? 1.0f : 0.0f;
        *(float4*)(o + (size_t)i * 4) = f;
    }
}

// ---------------- launch -----------------------------------------------------
extern "C" void kernel_launch(void* const* d_in, const int* in_sizes, int n_in,
                              void* d_out, int out_size) {
    const float* x  = (const float*)d_in[0];
    const float* W  = (const float*)d_in[1];
    const float* b  = (const float*)d_in[2];
    const float* al = (const float*)d_in[3];
    const float* ar = (const float*)d_in[4];
    const void*  m  = d_in[5];
    float* out = (float*)d_out;

    detect_mask_fmt<<<1, 32>>>((const unsigned int*)m);
    mask_canon<<<(NN * NN) / 256, 256>>>(m);
    gemm_xe<<<dim3(32, 8), 256>>>(x, W, b);
    hlr_kernel<<<4096, 256>>>(al, ar);
    gat_attn<<<dim3(128, 8), 256>>>(out);

    const int OUT_ELEMS  = NN * KFP;        // 2097152
    const int MASK_ELEMS = NN * NN;         // 16777216
    if (out_size >= OUT_ELEMS + MASK_ELEMS) {
        int n4 = MASK_ELEMS / 4;
        mask_to_float<<<(n4 + 255) / 256, 256>>>(out + OUT_ELEMS, n4);
    }
}

// round 5
// speedup vs baseline: 2.3437x; 2.3437x over previous
#include <cuda_runtime.h>
#include <cuda_bf16.h>
#include <cstdint>

#define NN   4096
#define FF   256
#define KH   8
#define FPD  64
#define KFP  512   // K*FP

// ---------------- scratch (static device globals; no allocation) -------------
__device__ float g_xe[NN * KFP];                  // 8 MB: xe[n][k*64+f]
__device__ float g_hl[KH * NN];                   // hl[k][n]
__device__ float g_hr[KH * NN];                   // hr[k][n]
__device__ unsigned int g_maskbT[(NN / 32) * NN]; // 2 MB bits: [m_word][n]
__device__ int g_mask_fmt;                        // 0=uint8, else 4-byte words
__device__ __nv_bfloat16 g_xeT_hi[KH * FPD * NN]; // 4 MB: hi(xe)[k][f][n]
__device__ __nv_bfloat16 g_xeT_lo[KH * FPD * NN]; // 4 MB: lo(xe)[k][f][n]

// =================== helpers (baseline PTX only: ldmatrix + mma.sync) =======
__device__ __forceinline__ uint32_t smem_u32(const void* p) {
    uint32_t a;
    asm("{ .reg .u64 t; cvta.to.shared.u64 t, %1; cvt.u32.u64 %0, t; }" : "=r"(a) : "l"(p));
    return a;
}
__device__ __forceinline__ unsigned short f2bf(float f) {
    unsigned short r;
    asm("cvt.rn.bf16.f32 %0, %1;" : "=h"(r) : "f"(f));
    return r;
}
// pack bf16x2: lo-half = cvt(x), hi-half = cvt(y)
__device__ __forceinline__ uint32_t bf16x2(float x, float y) {
    uint32_t r;
    asm("cvt.rn.bf16x2.f32 %0, %1, %2;" : "=r"(r) : "f"(y), "f"(x));
    return r;
}
#define LDSM4(R0, R1, R2, R3, A) \
    asm volatile("ldmatrix.sync.aligned.m8n8.x4.shared.b16 {%0,%1,%2,%3}, [%4];" \
                 : "=r"(R0), "=r"(R1), "=r"(R2), "=r"(R3) : "r"(A))
#define MMA16816(D, A0, A1, A2, A3, B0, B1) \
    asm volatile("mma.sync.aligned.m16n8k16.row.col.f32.bf16.bf16.f32 " \
                 "{%0,%1,%2,%3}, {%4,%5,%6,%7}, {%8,%9}, {%0,%1,%2,%3};" \
                 : "+f"((D)[0]), "+f"((D)[1]), "+f"((D)[2]), "+f"((D)[3]) \
                 : "r"(A0), "r"(A1), "r"(A2), "r"(A3), "r"(B0), "r"(B1))

__device__ __forceinline__ float pcalc(float hl, float hr, unsigned bit) {
    float s = hl + hr;
    float l = fmaxf(s, 0.2f * s);       // LeakyReLU(0.2)
    float e = __expf(l);
    return bit ? e : 0.0f;              // masked -> exactly 0
}

// ---------------- Kernel 0: probe mask dtype --------------------------------
// uint8-packed bool vs 4-byte (int32/float32) words. Random 0/1 content makes
// them separable in the first 4096 words (self-loop guarantees nonzero).
__global__ void detect_mask_fmt(const unsigned int* __restrict__ m) {
    int lane = threadIdx.x;
    bool not_i32 = false, not_f32 = false;
    for (int i = lane; i < 4096; i += 32) {
        unsigned int w = m[i];
        if (w > 1u) not_i32 = true;
        if (w != 0u && w != 0x3F800000u) not_f32 = true;
    }
    unsigned a = __ballot_sync(0xFFFFFFFFu, not_i32);
    unsigned b = __ballot_sync(0xFFFFFFFFu, not_f32);
    if (lane == 0) g_mask_fmt = (a == 0u) ? 1 : ((b == 0u) ? 2 : 0);
}

// ---------------- Kernel 0b: mask -> transposed bitfield --------------------
// g_maskbT[wm * NN + n], bit j of word = mask[n][32*wm + j]
__global__ void __launch_bounds__(256) mask_canon_bits(const void* __restrict__ m) {
    int idx = blockIdx.x * 256 + threadIdx.x;   // 0..524287
    int n  = idx >> 7;
    int wm = idx & 127;
    unsigned bits = 0;
    if (g_mask_fmt != 0) {
        const uint4* p = (const uint4*)((const unsigned int*)m + (size_t)n * NN + wm * 32);
#pragma unroll
        for (int q = 0; q < 8; q++) {
            uint4 v = p[q];
            bits |= (v.x != 0u) << (q * 4 + 0);
            bits |= (v.y != 0u) << (q * 4 + 1);
            bits |= (v.z != 0u) << (q * 4 + 2);
            bits |= (v.w != 0u) << (q * 4 + 3);
        }
    } else {
        const uint4* p = (const uint4*)((const unsigned char*)m + (size_t)n * NN + wm * 32);
#pragma unroll
        for (int q = 0; q < 2; q++) {
            uint4 v = p[q];
            unsigned w[4] = {v.x, v.y, v.z, v.w};
#pragma unroll
            for (int c = 0; c < 4; c++)
#pragma unroll
                for (int e = 0; e < 4; e++)
                    bits |= (((w[c] >> (e * 8)) & 0xFFu) != 0u) << (q * 16 + c * 4 + e);
        }
    }
    g_maskbT[(size_t)wm * NN + n] = bits;
}

// ---------------- Kernel A: xe = x @ W^T + b, plus bf16 hi/lo transpose -----
__global__ void __launch_bounds__(256) gemm_xe(const float* __restrict__ x,
                                               const float* __restrict__ W,
                                               const float* __restrict__ b) {
    __shared__ float a_s[16][128];
    __shared__ float b_s[16][64];
    const int tid = threadIdx.x;
    const int tx = tid & 15;
    const int ty = tid >> 4;
    const int row0 = blockIdx.x * 128;
    const int col0 = blockIdx.y * 64;

    float acc[8][4];
#pragma unroll
    for (int i = 0; i < 8; i++)
#pragma unroll
        for (int j = 0; j < 4; j++) acc[i][j] = 0.0f;

    for (int k0 = 0; k0 < FF; k0 += 16) {
#pragma unroll
        for (int u = 0; u < 2; u++) {
            int f4 = tid * 2 + u;
            int r  = f4 >> 2;
            int c4 = f4 & 3;
            float4 v = *(const float4*)&x[(size_t)(row0 + r) * FF + k0 + c4 * 4];
            a_s[c4 * 4 + 0][r] = v.x; a_s[c4 * 4 + 1][r] = v.y;
            a_s[c4 * 4 + 2][r] = v.z; a_s[c4 * 4 + 3][r] = v.w;
        }
        {
            int o  = tid >> 2;
            int c4 = tid & 3;
            float4 v = *(const float4*)&W[(size_t)(col0 + o) * FF + k0 + c4 * 4];
            b_s[c4 * 4 + 0][o] = v.x; b_s[c4 * 4 + 1][o] = v.y;
            b_s[c4 * 4 + 2][o] = v.z; b_s[c4 * 4 + 3][o] = v.w;
        }
        __syncthreads();
#pragma unroll
        for (int kk = 0; kk < 16; kk++) {
            float a_f[8], b_f[4];
#pragma unroll
            for (int i = 0; i < 8; i++) a_f[i] = a_s[kk][ty * 8 + i];
#pragma unroll
            for (int j = 0; j < 4; j++) b_f[j] = b_s[kk][tx * 4 + j];
#pragma unroll
            for (int i = 0; i < 8; i++)
#pragma unroll
                for (int j = 0; j < 4; j++) acc[i][j] += a_f[i] * b_f[j];
        }
        __syncthreads();
    }
    float4 bias = *(const float4*)&b[col0 + tx * 4];
#pragma unroll
    for (int i = 0; i < 8; i++) {
        acc[i][0] += bias.x; acc[i][1] += bias.y;
        acc[i][2] += bias.z; acc[i][3] += bias.w;
    }
    // fp32 xe (row-major): used by hlr
#pragma unroll
    for (int i = 0; i < 8; i++) {
        float4 v = make_float4(acc[i][0], acc[i][1], acc[i][2], acc[i][3]);
        *(float4*)&g_xe[(size_t)(row0 + ty * 8 + i) * KFP + col0 + tx * 4] = v;
    }
    // bf16 hi/lo split transpose: g_xeT_*[k][f][n]  (k = blockIdx.y, f = tx*4+j)
#pragma unroll
    for (int j = 0; j < 4; j++) {
        uint32_t hp[4], lp[4];
#pragma unroll
        for (int i2 = 0; i2 < 4; i2++) {
            float v0 = acc[2 * i2][j], v1 = acc[2 * i2 + 1][j];
            uint32_t b0 = __float_as_uint(v0), b1 = __float_as_uint(v1);
            hp[i2] = __byte_perm(b0, b1, 0x7632);               // trunc-to-bf16 pair
            float l0 = v0 - __uint_as_float(b0 & 0xFFFF0000u);
            float l1 = v1 - __uint_as_float(b1 & 0xFFFF0000u);
            lp[i2] = bf16x2(l0, l1);
        }
        size_t base = ((size_t)(blockIdx.y * FPD + tx * 4 + j)) * NN + row0 + ty * 8;
        *(uint4*)&g_xeT_hi[base] = make_uint4(hp[0], hp[1], hp[2], hp[3]);
        *(uint4*)&g_xeT_lo[base] = make_uint4(lp[0], lp[1], lp[2], lp[3]);
    }
}

// ---------------- Kernel B: hl[k][n], hr[k][n] ------------------------------
__global__ void __launch_bounds__(256) hlr_kernel(const float* __restrict__ al,
                                                  const float* __restrict__ ar) {
    int wid  = blockIdx.x * 8 + (threadIdx.x >> 5);
    int lane = threadIdx.x & 31;
    int k = wid >> 12;
    int n = wid & 4095;
    float x0 = g_xe[(size_t)n * KFP + k * FPD + lane];
    float x1 = g_xe[(size_t)n * KFP + k * FPD + 32 + lane];
    float l = x0 * al[k * FPD + lane] + x1 * al[k * FPD + 32 + lane];
    float r = x0 * ar[k * FPD + lane] + x1 * ar[k * FPD + 32 + lane];
#pragma unroll
    for (int off = 16; off; off >>= 1) {
        l += __shfl_xor_sync(0xFFFFFFFFu, l, off);
        r += __shfl_xor_sync(0xFFFFFFFFu, r, off);
    }
    if (lane == 0) {
        g_hl[k * NN + n] = l;
        g_hr[k * NN + n] = r;
    }
}

// ---------------- Kernel C: attention via mma.sync bf16 (split 3xMMA) -------
// CTA = (head k, 128 n-rows). Warp w owns rows 16w..16w+15, all 64 f-cols.
// Per 128-m chunk: lanes compute their mma A-fragment p-values directly in
// registers (exp of additive scores, mask via bitfield); V tiles staged in
// SMEM [f][m] and fed via ldmatrix as the col-major B operand.
// D += Phi*Vhi + Phi*Vlo + Plo*Vhi  (residual Plo*Vlo ~ 2^-16 relative).
__global__ void __launch_bounds__(256, 2) gat_attn_mma(float* __restrict__ out) {
    __shared__ __align__(16) __nv_bfloat16 s_vhi[64 * 136];  // pad 8 halves/row
    __shared__ __align__(16) __nv_bfloat16 s_vlo[64 * 136];
    __shared__ float s_hr[128];
    __shared__ uint32_t s_mb[128 * 4];

    const int tid  = threadIdx.x;
    const int lane = tid & 31;
    const int warp = tid >> 5;
    const int k    = blockIdx.y;
    const int n0   = blockIdx.x * 128;
    const int g    = lane >> 2;          // row group 0..7
    const int q    = lane & 3;           // col group 0..3
    const int r0   = warp * 16 + g;
    const int r1   = r0 + 8;

    const float hl0 = g_hl[k * NN + n0 + r0];
    const float hl1 = g_hl[k * NN + n0 + r1];

    float d[8][4];
#pragma unroll
    for (int nt = 0; nt < 8; nt++)
#pragma unroll
        for (int e = 0; e < 4; e++) d[nt][e] = 0.0f;
    float rs0 = 0.0f, rs1 = 0.0f;

    const uint32_t vb_hi = smem_u32(s_vhi);
    const uint32_t vb_lo = smem_u32(s_vlo);
    // ldmatrix.x4 per-lane source row/byte-offset (matrices: f-lo/k-lo,
    // f-lo/k-hi, f-hi/k-lo, f-hi/k-hi)
    const uint32_t lm_row  = ((lane & 16) >> 1) + (lane & 7);   // 0..15
    const uint32_t lm_koff = (lane & 8) ? 16u : 0u;

#pragma unroll 1
    for (int c = 0; c < 32; c++) {
        const int m0 = c * 128;
        // ---- stage V hi/lo (64 f x 128 m, 16B granules) ----
#pragma unroll
        for (int u = 0; u < 8; u++) {
            int idx = u * 256 + tid;             // 0..2047
            int sel = idx >> 10;
            int rem = idx & 1023;
            int f   = rem >> 4;
            int mo  = (rem & 15) * 8;
            const __nv_bfloat16* src = (sel ? g_xeT_lo : g_xeT_hi)
                + ((size_t)(k * FPD + f)) * NN + m0 + mo;
            uint4 v = *(const uint4*)src;
            *(uint4*)((sel ? s_vlo : s_vhi) + f * 136 + mo) = v;
        }
        if (tid < 128) s_hr[tid] = g_hr[k * NN + m0 + tid];
#pragma unroll
        for (int i = 0; i < 2; i++) {
            int idx = tid + i * 256;             // 0..511
            int w = idx >> 7, r = idx & 127;
            s_mb[r * 4 + w] = g_maskbT[(size_t)(m0 / 32 + w) * NN + n0 + r];
        }
        __syncthreads();

        uint32_t mb0[4], mb1[4];
        *(uint4*)mb0 = *(const uint4*)&s_mb[r0 * 4];
        *(uint4*)mb1 = *(const uint4*)&s_mb[r1 * 4];

#pragma unroll
        for (int t = 0; t < 8; t++) {
            // scores for this lane's A-fragment slots
            float2 hA = *(const float2*)&s_hr[t * 16 + q * 2];
            float2 hB = *(const float2*)&s_hr[t * 16 + q * 2 + 8];
            uint32_t w0 = mb0[t >> 1], w1 = mb1[t >> 1];
            int sh = (t & 1) * 16 + q * 2;
            float p00 = pcalc(hl0, hA.x, (w0 >> sh) & 1u);
            float p01 = pcalc(hl0, hA.y, (w0 >> (sh + 1)) & 1u);
            float p02 = pcalc(hl0, hB.x, (w0 >> (sh + 8)) & 1u);
            float p03 = pcalc(hl0, hB.y, (w0 >> (sh + 9)) & 1u);
            float p10 = pcalc(hl1, hA.x, (w1 >> sh) & 1u);
            float p11 = pcalc(hl1, hA.y, (w1 >> (sh + 1)) & 1u);
            float p12 = pcalc(hl1, hB.x, (w1 >> (sh + 8)) & 1u);
            float p13 = pcalc(hl1, hB.y, (w1 >> (sh + 9)) & 1u);
            rs0 += (p00 + p01) + (p02 + p03);
            rs1 += (p10 + p11) + (p12 + p13);

            // A fragments: hi = truncated bf16 (exact split), lo = remainder
            uint32_t b00 = __float_as_uint(p00), b01 = __float_as_uint(p01);
            uint32_t b10 = __float_as_uint(p10), b11 = __float_as_uint(p11);
            uint32_t b02 = __float_as_uint(p02), b03 = __float_as_uint(p03);
            uint32_t b12 = __float_as_uint(p12), b13 = __float_as_uint(p13);
            uint32_t ah0 = __byte_perm(b00, b01, 0x7632);
            uint32_t ah1 = __byte_perm(b10, b11, 0x7632);
            uint32_t ah2 = __byte_perm(b02, b03, 0x7632);
            uint32_t ah3 = __byte_perm(b12, b13, 0x7632);
            uint32_t al0 = bf16x2(p00 - __uint_as_float(b00 & 0xFFFF0000u),
                                  p01 - __uint_as_float(b01 & 0xFFFF0000u));
            uint32_t al1 = bf16x2(p10 - __uint_as_float(b10 & 0xFFFF0000u),
                                  p11 - __uint_as_float(b11 & 0xFFFF0000u));
            uint32_t al2 = bf16x2(p02 - __uint_as_float(b02 & 0xFFFF0000u),
                                  p03 - __uint_as_float(b03 & 0xFFFF0000u));
            uint32_t al3 = bf16x2(p12 - __uint_as_float(b12 & 0xFFFF0000u),
                                  p13 - __uint_as_float(b13 & 0xFFFF0000u));

#pragma unroll
            for (int pr = 0; pr < 4; pr++) {
                uint32_t a = (pr * 16 + lm_row) * 272 + t * 32 + lm_koff;
                uint32_t vh0, vh1, vh2, vh3, vl0, vl1, vl2, vl3;
                LDSM4(vh0, vh1, vh2, vh3, vb_hi + a);
                LDSM4(vl0, vl1, vl2, vl3, vb_lo + a);
                MMA16816(d[2 * pr],     ah0, ah1, ah2, ah3, vh0, vh1);
                MMA16816(d[2 * pr],     ah0, ah1, ah2, ah3, vl0, vl1);
                MMA16816(d[2 * pr],     al0, al1, al2, al3, vh0, vh1);
                MMA16816(d[2 * pr + 1], ah0, ah1, ah2, ah3, vh2, vh3);
                MMA16816(d[2 * pr + 1], ah0, ah1, ah2, ah3, vl2, vl3);
                MMA16816(d[2 * pr + 1], al0, al1, al2, al3, vh2, vh3);
            }
        }
        __syncthreads();
    }

    // ---- epilogue: rowsum (quad reduce), normalize, double-ELU, store ----
    rs0 += __shfl_xor_sync(0xFFFFFFFFu, rs0, 1);
    rs0 += __shfl_xor_sync(0xFFFFFFFFu, rs0, 2);
    rs1 += __shfl_xor_sync(0xFFFFFFFFu, rs1, 1);
    rs1 += __shfl_xor_sync(0xFFFFFFFFu, rs1, 2);
    const float i0 = 1.0f / rs0;
    const float i1 = 1.0f / rs1;
    float* o0 = out + (size_t)(n0 + r0) * KFP + k * FPD + 2 * q;
    float* o1 = out + (size_t)(n0 + r1) * KFP + k * FPD + 2 * q;
#pragma unroll
    for (int nt = 0; nt < 8; nt++) {
        float z0 = d[nt][0] * i0, z1 = d[nt][1] * i0;
        float z2 = d[nt][2] * i1, z3 = d[nt][3] * i1;
        z0 = z0 > 0.f ? z0 : expm1f(z0); z0 = z0 > 0.f ? z0 : expm1f(z0);
        z1 = z1 > 0.f ? z1 : expm1f(z1); z1 = z1 > 0.f ? z1 : expm1f(z1);
        z2 = z2 > 0.f ? z2 : expm1f(z2); z2 = z2 > 0.f ? z2 : expm1f(z2);
        z3 = z3 > 0.f ? z3 : expm1f(z3); z3 = z3 > 0.f ? z3 : expm1f(z3);
        *(float2*)(o0 + nt * 8) = make_float2(z0, z1);
        *(float2*)(o1 + nt * 8) = make_float2(z2, z3);
    }
}

// ---------------- optional: mask passthrough as float -----------------------
__global__ void mask_to_float(float* __restrict__ o, int n) {
    int i = blockIdx.x * blockDim.x + threadIdx.x;
    if (i < n) {
        int row = i >> 12, m = i & 4095;
        unsigned b = (g_maskbT[(size_t)(m >> 5) * NN + row] >> (m & 31)) & 1u;
        o[i] = (float)b;
    }
}

// ---------------- launch -----------------------------------------------------
extern "C" void kernel_launch(void* const* d_in, const int* in_sizes, int n_in,
                              void* d_out, int out_size) {
    const float* x  = (const float*)d_in[0];
    const float* W  = (const float*)d_in[1];
    const float* b  = (const float*)d_in[2];
    const float* al = (const float*)d_in[3];
    const float* ar = (const float*)d_in[4];
    const void*  m  = d_in[5];
    float* out = (float*)d_out;

    detect_mask_fmt<<<1, 32>>>((const unsigned int*)m);
    mask_canon_bits<<<(NN * NN / 32) / 256, 256>>>(m);
    gemm_xe<<<dim3(32, 8), 256>>>(x, W, b);
    hlr_kernel<<<4096, 256>>>(al, ar);
    gat_attn_mma<<<dim3(32, 8), 256>>>(out);

    const int OUT_ELEMS  = NN * KFP;
    const int MASK_ELEMS = NN * NN;
    if (out_size >= OUT_ELEMS + MASK_ELEMS) {
        mask_to_float<<<(MASK_ELEMS + 255) / 256, 256>>>(out + OUT_ELEMS, MASK_ELEMS);
    }
}

// round 6
// speedup vs baseline: 2.5455x; 1.0861x over previous
#include <cuda_runtime.h>
#include <cuda_bf16.h>
#include <cstdint>

#define NN   4096
#define FF   256
#define KH   8
#define FPD  64
#define KFP  512   // K*FP

// ---------------- scratch (static device globals; no allocation) -------------
__device__ float g_hl[KH * NN];                   // hl[k][n]
__device__ float g_hr[KH * NN];                   // hr[k][n]
__device__ unsigned int g_maskbT[(NN / 32) * NN]; // 2 MB bits: [m_word][n]
__device__ int g_mask_fmt;                        // 0=uint8, else 4-byte words
__device__ __nv_bfloat16 g_xeT_hi[KH * FPD * NN]; // 4 MB: hi(xe)[k][f][n]
__device__ __nv_bfloat16 g_xeT_lo[KH * FPD * NN]; // 4 MB: lo(xe)[k][f][n]

// =================== helpers (baseline PTX only: ldmatrix + mma.sync) =======
__device__ __forceinline__ uint32_t smem_u32(const void* p) {
    uint32_t a;
    asm("{ .reg .u64 t; cvta.to.shared.u64 t, %1; cvt.u32.u64 %0, t; }" : "=r"(a) : "l"(p));
    return a;
}
// pack bf16x2: lo-half = cvt(x), hi-half = cvt(y)
__device__ __forceinline__ uint32_t bf16x2(float x, float y) {
    uint32_t r;
    asm("cvt.rn.bf16x2.f32 %0, %1, %2;" : "=r"(r) : "f"(y), "f"(x));
    return r;
}
#define LDSM4(R0, R1, R2, R3, A) \
    asm volatile("ldmatrix.sync.aligned.m8n8.x4.shared.b16 {%0,%1,%2,%3}, [%4];" \
                 : "=r"(R0), "=r"(R1), "=r"(R2), "=r"(R3) : "r"(A))
#define MMA16816(D, A0, A1, A2, A3, B0, B1) \
    asm volatile("mma.sync.aligned.m16n8k16.row.col.f32.bf16.bf16.f32 " \
                 "{%0,%1,%2,%3}, {%4,%5,%6,%7}, {%8,%9}, {%0,%1,%2,%3};" \
                 : "+f"((D)[0]), "+f"((D)[1]), "+f"((D)[2]), "+f"((D)[3]) \
                 : "r"(A0), "r"(A1), "r"(A2), "r"(A3), "r"(B0), "r"(B1))

__device__ __forceinline__ float pcalc(float hl, float hr, unsigned bit) {
    float s = hl + hr;
    float l = fmaxf(s, 0.2f * s);       // LeakyReLU(0.2)
    float e = __expf(l);
    return bit ? e : 0.0f;              // masked -> exactly 0
}

// ---------------- Kernel 0: probe mask dtype --------------------------------
__global__ void detect_mask_fmt(const unsigned int* __restrict__ m) {
    int lane = threadIdx.x;
    bool not_i32 = false, not_f32 = false;
    for (int i = lane; i < 4096; i += 32) {
        unsigned int w = m[i];
        if (w > 1u) not_i32 = true;
        if (w != 0u && w != 0x3F800000u) not_f32 = true;
    }
    unsigned a = __ballot_sync(0xFFFFFFFFu, not_i32);
    unsigned b = __ballot_sync(0xFFFFFFFFu, not_f32);
    if (lane == 0) g_mask_fmt = (a == 0u) ? 1 : ((b == 0u) ? 2 : 0);
}

// ---------------- Kernel 0b: mask -> transposed bitfield --------------------
// g_maskbT[wm * NN + n], bit j of word = mask[n][32*wm + j]
__global__ void __launch_bounds__(256) mask_canon_bits(const void* __restrict__ m) {
    int idx = blockIdx.x * 256 + threadIdx.x;   // 0..524287
    int n  = idx >> 7;
    int wm = idx & 127;
    unsigned bits = 0;
    if (g_mask_fmt != 0) {
        const uint4* p = (const uint4*)((const unsigned int*)m + (size_t)n * NN + wm * 32);
#pragma unroll
        for (int q = 0; q < 8; q++) {
            uint4 v = p[q];
            bits |= (v.x != 0u) << (q * 4 + 0);
            bits |= (v.y != 0u) << (q * 4 + 1);
            bits |= (v.z != 0u) << (q * 4 + 2);
            bits |= (v.w != 0u) << (q * 4 + 3);
        }
    } else {
        const uint4* p = (const uint4*)((const unsigned char*)m + (size_t)n * NN + wm * 32);
#pragma unroll
        for (int q = 0; q < 2; q++) {
            uint4 v = p[q];
            unsigned w[4] = {v.x, v.y, v.z, v.w};
#pragma unroll
            for (int c = 0; c < 4; c++)
#pragma unroll
                for (int e = 0; e < 4; e++)
                    bits |= (((w[c] >> (e * 8)) & 0xFFu) != 0u) << (q * 16 + c * 4 + e);
        }
    }
    g_maskbT[(size_t)wm * NN + n] = bits;
}

// ---------------- Kernel A: xe GEMM + fused hl/hr + bf16 hi/lo transpose ----
// Block = 128 rows x one head (64 f). Epilogue computes hl/hr via in-warp
// reduction (no fp32 xe round-trip needed at all).
__global__ void __launch_bounds__(256) gemm_xe(const float* __restrict__ x,
                                               const float* __restrict__ W,
                                               const float* __restrict__ b,
                                               const float* __restrict__ al,
                                               const float* __restrict__ ar) {
    __shared__ float a_s[16][128];
    __shared__ float b_s[16][64];
    const int tid = threadIdx.x;
    const int tx = tid & 15;
    const int ty = tid >> 4;
    const int row0 = blockIdx.x * 128;
    const int k    = blockIdx.y;          // head
    const int col0 = k * 64;

    float acc[8][4];
#pragma unroll
    for (int i = 0; i < 8; i++)
#pragma unroll
        for (int j = 0; j < 4; j++) acc[i][j] = 0.0f;

    for (int k0 = 0; k0 < FF; k0 += 16) {
#pragma unroll
        for (int u = 0; u < 2; u++) {
            int f4 = tid * 2 + u;
            int r  = f4 >> 2;
            int c4 = f4 & 3;
            float4 v = *(const float4*)&x[(size_t)(row0 + r) * FF + k0 + c4 * 4];
            a_s[c4 * 4 + 0][r] = v.x; a_s[c4 * 4 + 1][r] = v.y;
            a_s[c4 * 4 + 2][r] = v.z; a_s[c4 * 4 + 3][r] = v.w;
        }
        {
            int o  = tid >> 2;
            int c4 = tid & 3;
            float4 v = *(const float4*)&W[(size_t)(col0 + o) * FF + k0 + c4 * 4];
            b_s[c4 * 4 + 0][o] = v.x; b_s[c4 * 4 + 1][o] = v.y;
            b_s[c4 * 4 + 2][o] = v.z; b_s[c4 * 4 + 3][o] = v.w;
        }
        __syncthreads();
#pragma unroll
        for (int kk = 0; kk < 16; kk++) {
            float a_f[8], b_f[4];
#pragma unroll
            for (int i = 0; i < 8; i++) a_f[i] = a_s[kk][ty * 8 + i];
#pragma unroll
            for (int j = 0; j < 4; j++) b_f[j] = b_s[kk][tx * 4 + j];
#pragma unroll
            for (int i = 0; i < 8; i++)
#pragma unroll
                for (int j = 0; j < 4; j++) acc[i][j] += a_f[i] * b_f[j];
        }
        __syncthreads();
    }
    float4 bias = *(const float4*)&b[col0 + tx * 4];
#pragma unroll
    for (int i = 0; i < 8; i++) {
        acc[i][0] += bias.x; acc[i][1] += bias.y;
        acc[i][2] += bias.z; acc[i][3] += bias.w;
    }
    // ---- fused hl/hr: partial dot over this thread's 4 f, reduce over tx ----
    float4 al4 = *(const float4*)&al[k * FPD + tx * 4];
    float4 ar4 = *(const float4*)&ar[k * FPD + tx * 4];
#pragma unroll
    for (int i = 0; i < 8; i++) {
        float l = acc[i][0] * al4.x + acc[i][1] * al4.y + acc[i][2] * al4.z + acc[i][3] * al4.w;
        float r = acc[i][0] * ar4.x + acc[i][1] * ar4.y + acc[i][2] * ar4.z + acc[i][3] * ar4.w;
#pragma unroll
        for (int off = 8; off; off >>= 1) {
            l += __shfl_xor_sync(0xFFFFFFFFu, l, off);
            r += __shfl_xor_sync(0xFFFFFFFFu, r, off);
        }
        if (tx == 0) {
            g_hl[k * NN + row0 + ty * 8 + i] = l;
            g_hr[k * NN + row0 + ty * 8 + i] = r;
        }
    }
    // ---- bf16 hi/lo split transpose: g_xeT_*[k][f][n] ----
#pragma unroll
    for (int j = 0; j < 4; j++) {
        uint32_t hp[4], lp[4];
#pragma unroll
        for (int i2 = 0; i2 < 4; i2++) {
            float v0 = acc[2 * i2][j], v1 = acc[2 * i2 + 1][j];
            uint32_t b0 = __float_as_uint(v0), b1 = __float_as_uint(v1);
            hp[i2] = __byte_perm(b0, b1, 0x7632);               // trunc-to-bf16 pair
            float l0 = v0 - __uint_as_float(b0 & 0xFFFF0000u);
            float l1 = v1 - __uint_as_float(b1 & 0xFFFF0000u);
            lp[i2] = bf16x2(l0, l1);
        }
        size_t base = ((size_t)(k * FPD + tx * 4 + j)) * NN + row0 + ty * 8;
        *(uint4*)&g_xeT_hi[base] = make_uint4(hp[0], hp[1], hp[2], hp[3]);
        *(uint4*)&g_xeT_lo[base] = make_uint4(lp[0], lp[1], lp[2], lp[3]);
    }
}

// ---------------- Kernel C: attention via mma.sync bf16 (split 3xMMA) -------
// CTA = (head k, 128 n-rows). Warp w owns rows 16w..16w+15, all 64 f.
// m-chunks of 64, double-buffered in SMEM: prefetch chunk c+1 into regs while
// computing chunk c, STS to alternate stage, ONE syncthreads per chunk.
// D += Phi*Vhi + Phi*Vlo + Plo*Vhi  (residual Plo*Vlo ~ 2^-18 relative).
#define MCH 64
__global__ void __launch_bounds__(256, 2) gat_attn_mma(float* __restrict__ out) {
    __shared__ __align__(16) __nv_bfloat16 s_vhi[2][MCH * 72];  // rows padded to 72 halves
    __shared__ __align__(16) __nv_bfloat16 s_vlo[2][MCH * 72];
    __shared__ float s_hr[2][MCH];
    __shared__ uint32_t s_mb[2][128 * 2];

    const int tid  = threadIdx.x;
    const int lane = tid & 31;
    const int warp = tid >> 5;
    const int k    = blockIdx.y;
    const int n0   = blockIdx.x * 128;
    const int g    = lane >> 2;
    const int q    = lane & 3;
    const int r0   = warp * 16 + g;
    const int r1   = r0 + 8;

    const float hl0 = g_hl[k * NN + n0 + r0];
    const float hl1 = g_hl[k * NN + n0 + r1];

    float d[8][4];
#pragma unroll
    for (int nt = 0; nt < 8; nt++)
#pragma unroll
        for (int e = 0; e < 4; e++) d[nt][e] = 0.0f;
    float rs0 = 0.0f, rs1 = 0.0f;

    const uint32_t vb_hi0 = smem_u32(s_vhi[0]);
    const uint32_t vb_lo0 = smem_u32(s_vlo[0]);
    const uint32_t lm_row  = ((lane & 16) >> 1) + (lane & 7);   // 0..15
    const uint32_t lm_koff = (lane & 8) ? 16u : 0u;

    // prefetch decode (constant per thread)
    const int pf_sel = tid >> 9;                  // always 0 for 256 thr; sel from idx
    (void)pf_sel;
    // per-u: idx = u*256+tid; sel = idx>>9; rem = idx&511; f = rem>>3; mo = (rem&7)*8
    const int pf_r  = tid & 127;                  // mask row
    const int pf_w  = tid >> 7;                   // mask word (0..1)

    uint4 vreg[4];
    float hreg;
    uint32_t mreg;

    // ---- prologue: prefetch chunk 0 ----
    {
        const int m0 = 0;
#pragma unroll
        for (int u = 0; u < 4; u++) {
            int idx = u * 256 + tid;
            int sel = idx >> 9;
            int rem = idx & 511;
            int f = rem >> 3, mo = (rem & 7) * 8;
            vreg[u] = *(const uint4*)((sel ? g_xeT_lo : g_xeT_hi)
                        + ((size_t)(k * FPD + f)) * NN + m0 + mo);
        }
        hreg = (tid < MCH) ? g_hr[k * NN + m0 + tid] : 0.0f;
        mreg = g_maskbT[(size_t)(m0 / 32 + pf_w) * NN + n0 + pf_r];
        // store to stage 0
#pragma unroll
        for (int u = 0; u < 4; u++) {
            int idx = u * 256 + tid;
            int sel = idx >> 9;
            int rem = idx & 511;
            int f = rem >> 3, mo = (rem & 7) * 8;
            *(uint4*)((sel ? s_vlo[0] : s_vhi[0]) + f * 72 + mo) = vreg[u];
        }
        if (tid < MCH) s_hr[0][tid] = hreg;
        s_mb[0][pf_r * 2 + pf_w] = mreg;
        __syncthreads();
    }

#pragma unroll 1
    for (int c = 0; c < NN / MCH; c++) {
        const int st = c & 1;
        const bool more = (c + 1 < NN / MCH);
        // ---- prefetch chunk c+1 into regs (overlaps MMA below) ----
        if (more) {
            const int m0 = (c + 1) * MCH;
#pragma unroll
            for (int u = 0; u < 4; u++) {
                int idx = u * 256 + tid;
                int sel = idx >> 9;
                int rem = idx & 511;
                int f = rem >> 3, mo = (rem & 7) * 8;
                vreg[u] = *(const uint4*)((sel ? g_xeT_lo : g_xeT_hi)
                            + ((size_t)(k * FPD + f)) * NN + m0 + mo);
            }
            hreg = (tid < MCH) ? g_hr[k * NN + m0 + tid] : 0.0f;
            mreg = g_maskbT[(size_t)(m0 / 32 + pf_w) * NN + n0 + pf_r];
        }

        // ---- compute on stage st ----
        uint32_t mb0[2], mb1[2];
        *(uint2*)mb0 = *(const uint2*)&s_mb[st][r0 * 2];
        *(uint2*)mb1 = *(const uint2*)&s_mb[st][r1 * 2];
        const uint32_t vbh = vb_hi0 + st * (MCH * 72 * 2);
        const uint32_t vbl = vb_lo0 + st * (MCH * 72 * 2);

#pragma unroll
        for (int t = 0; t < 4; t++) {
            float2 hA = *(const float2*)&s_hr[st][t * 16 + q * 2];
            float2 hB = *(const float2*)&s_hr[st][t * 16 + q * 2 + 8];
            uint32_t w0 = mb0[t >> 1], w1 = mb1[t >> 1];
            int sh = (t & 1) * 16 + q * 2;
            float p00 = pcalc(hl0, hA.x, (w0 >> sh) & 1u);
            float p01 = pcalc(hl0, hA.y, (w0 >> (sh + 1)) & 1u);
            float p02 = pcalc(hl0, hB.x, (w0 >> (sh + 8)) & 1u);
            float p03 = pcalc(hl0, hB.y, (w0 >> (sh + 9)) & 1u);
            float p10 = pcalc(hl1, hA.x, (w1 >> sh) & 1u);
            float p11 = pcalc(hl1, hA.y, (w1 >> (sh + 1)) & 1u);
            float p12 = pcalc(hl1, hB.x, (w1 >> (sh + 8)) & 1u);
            float p13 = pcalc(hl1, hB.y, (w1 >> (sh + 9)) & 1u);
            rs0 += (p00 + p01) + (p02 + p03);
            rs1 += (p10 + p11) + (p12 + p13);

            uint32_t b00 = __float_as_uint(p00), b01 = __float_as_uint(p01);
            uint32_t b10 = __float_as_uint(p10), b11 = __float_as_uint(p11);
            uint32_t b02 = __float_as_uint(p02), b03 = __float_as_uint(p03);
            uint32_t b12 = __float_as_uint(p12), b13 = __float_as_uint(p13);
            uint32_t ah0 = __byte_perm(b00, b01, 0x7632);
            uint32_t ah1 = __byte_perm(b10, b11, 0x7632);
            uint32_t ah2 = __byte_perm(b02, b03, 0x7632);
            uint32_t ah3 = __byte_perm(b12, b13, 0x7632);
            uint32_t al0 = bf16x2(p00 - __uint_as_float(b00 & 0xFFFF0000u),
                                  p01 - __uint_as_float(b01 & 0xFFFF0000u));
            uint32_t al1 = bf16x2(p10 - __uint_as_float(b10 & 0xFFFF0000u),
                                  p11 - __uint_as_float(b11 & 0xFFFF0000u));
            uint32_t al2 = bf16x2(p02 - __uint_as_float(b02 & 0xFFFF0000u),
                                  p03 - __uint_as_float(b03 & 0xFFFF0000u));
            uint32_t al3 = bf16x2(p12 - __uint_as_float(b12 & 0xFFFF0000u),
                                  p13 - __uint_as_float(b13 & 0xFFFF0000u));

#pragma unroll
            for (int pr = 0; pr < 4; pr++) {
                uint32_t a = (pr * 16 + lm_row) * 144 + t * 32 + lm_koff;
                uint32_t vh0, vh1, vh2, vh3, vl0, vl1, vl2, vl3;
                LDSM4(vh0, vh1, vh2, vh3, vbh + a);
                LDSM4(vl0, vl1, vl2, vl3, vbl + a);
                MMA16816(d[2 * pr],     ah0, ah1, ah2, ah3, vh0, vh1);
                MMA16816(d[2 * pr],     ah0, ah1, ah2, ah3, vl0, vl1);
                MMA16816(d[2 * pr],     al0, al1, al2, al3, vh0, vh1);
                MMA16816(d[2 * pr + 1], ah0, ah1, ah2, ah3, vh2, vh3);
                MMA16816(d[2 * pr + 1], ah0, ah1, ah2, ah3, vl2, vl3);
                MMA16816(d[2 * pr + 1], al0, al1, al2, al3, vh2, vh3);
            }
        }

        // ---- store prefetched chunk to alternate stage ----
        if (more) {
            const int st1 = 1 - st;
#pragma unroll
            for (int u = 0; u < 4; u++) {
                int idx = u * 256 + tid;
                int sel = idx >> 9;
                int rem = idx & 511;
                int f = rem >> 3, mo = (rem & 7) * 8;
                *(uint4*)((sel ? s_vlo[st1] : s_vhi[st1]) + f * 72 + mo) = vreg[u];
            }
            if (tid < MCH) s_hr[st1][tid] = hreg;
            s_mb[st1][pf_r * 2 + pf_w] = mreg;
            __syncthreads();
        }
    }

    // ---- epilogue: rowsum (quad reduce), normalize, double-ELU, store ----
    rs0 += __shfl_xor_sync(0xFFFFFFFFu, rs0, 1);
    rs0 += __shfl_xor_sync(0xFFFFFFFFu, rs0, 2);
    rs1 += __shfl_xor_sync(0xFFFFFFFFu, rs1, 1);
    rs1 += __shfl_xor_sync(0xFFFFFFFFu, rs1, 2);
    const float i0 = 1.0f / rs0;
    const float i1 = 1.0f / rs1;
    float* o0 = out + (size_t)(n0 + r0) * KFP + k * FPD + 2 * q;
    float* o1 = out + (size_t)(n0 + r1) * KFP + k * FPD + 2 * q;
#pragma unroll
    for (int nt = 0; nt < 8; nt++) {
        float z0 = d[nt][0] * i0, z1 = d[nt][1] * i0;
        float z2 = d[nt][2] * i1, z3 = d[nt][3] * i1;
        z0 = z0 > 0.f ? z0 : expm1f(z0); z0 = z0 > 0.f ? z0 : expm1f(z0);
        z1 = z1 > 0.f ? z1 : expm1f(z1); z1 = z1 > 0.f ? z1 : expm1f(z1);
        z2 = z2 > 0.f ? z2 : expm1f(z2); z2 = z2 > 0.f ? z2 : expm1f(z2);
        z3 = z3 > 0.f ? z3 : expm1f(z3); z3 = z3 > 0.f ? z3 : expm1f(z3);
        *(float2*)(o0 + nt * 8) = make_float2(z0, z1);
        *(float2*)(o1 + nt * 8) = make_float2(z2, z3);
    }
}

// ---------------- optional: mask passthrough as float -----------------------
__global__ void mask_to_float(float* __restrict__ o, int n) {
    int i = blockIdx.x * blockDim.x + threadIdx.x;
    if (i < n) {
        int row = i >> 12, m = i & 4095;
        unsigned b = (g_maskbT[(size_t)(m >> 5) * NN + row] >> (m & 31)) & 1u;
        o[i] = (float)b;
    }
}

// ---------------- launch -----------------------------------------------------
extern "C" void kernel_launch(void* const* d_in, const int* in_sizes, int n_in,
                              void* d_out, int out_size) {
    const float* x  = (const float*)d_in[0];
    const float* W  = (const float*)d_in[1];
    const float* b  = (const float*)d_in[2];
    const float* al = (const float*)d_in[3];
    const float* ar = (const float*)d_in[4];
    const void*  m  = d_in[5];
    float* out = (float*)d_out;

    detect_mask_fmt<<<1, 32>>>((const unsigned int*)m);
    mask_canon_bits<<<(NN * NN / 32) / 256, 256>>>(m);
    gemm_xe<<<dim3(32, 8), 256>>>(x, W, b, al, ar);
    gat_attn_mma<<<dim3(32, 8), 256>>>(out);

    const int OUT_ELEMS  = NN * KFP;
    const int MASK_ELEMS = NN * NN;
    if (out_size >= OUT_ELEMS + MASK_ELEMS) {
        mask_to_float<<<(MASK_ELEMS + 255) / 256, 256>>>(out + OUT_ELEMS, MASK_ELEMS);
    }
}